// round 14
// baseline (speedup 1.0000x reference)
#include <cuda_runtime.h>
#include <cuda_fp16.h>
#include <cstdint>
#include <cstddef>

// Harness PTX target is base sm_103 — no tcgen05. Tensor path: mma.sync f16 m16n8k16
// (fallback HMMA, rt~7.2 cyc/SMSP -> ~341us busy floor). Round 14: 2x2 warp grid
// (warp tile 64x64, A/B fragment redundancy 2x each) drops smem traffic below the
// HMMA floor. 128-thread CTAs, 2 CTAs/SM, R13 mbarrier pipeline kept verbatim.

// ---------------- problem constants ----------------
#define N_TOK   16384
#define F_DIM   1024
#define B_DIM   512
#define TILE_M  128
#define TILE_F  32
#define GCOLS   128          // 4 gates * TILE_F
#define KC      64           // K elements per chunk (128B fp16 rows)
#define NCHUNK  24           // 1536 / 64
#define THREADS 128
#define STAGES  3

// ---------------- smem layout ----------------
#define ABYTES      (TILE_M * KC * 2)          // 16384
#define BBYTES      (GCOLS * KC * 2)           // 16384
#define STAGE_BYTES (ABYTES + BBYTES)          // 32768
#define GSM_PITCH   36
#define GSM_BYTES   (4 * 128 * GSM_PITCH * 4)  // 73728 (epilogue, unions stages)
#define SM_BIAS     (STAGES * STAGE_BYTES)     // 98304
#define SM_MBAR     (SM_BIAS + 512)            // 6 mbarriers x 8B
#define SMEM_TOTAL  (SM_MBAR + 64)             // 98880  (x2 CTAs = 197760)

static_assert(GSM_BYTES <= STAGES * STAGE_BYTES, "epilogue union");
static_assert(2 * SMEM_TOTAL <= 227 * 1024, "2 CTAs/SM smem");

// ---------------- fp16 scratch ----------------
#define NH  (N_TOK * F_DIM)
#define NX  (N_TOK * B_DIM)
#define NWH (4 * F_DIM * F_DIM)
#define NWX (4 * F_DIM * B_DIM)
__device__ __half g_h [NH];
__device__ __half g_x [NX];
__device__ __half g_wh[NWH];
__device__ __half g_wx[NWX];

// ---------------- helpers ----------------
static __device__ __forceinline__ uint32_t smem_u32(const void* p) {
    uint32_t a;
    asm("{ .reg .u64 t; cvta.to.shared.u64 t, %1; cvt.u32.u64 %0, t; }" : "=r"(a) : "l"(p));
    return a;
}

static __device__ __forceinline__ void cp16(uint32_t dst, const void* src) {
    asm volatile("cp.async.cg.shared.global [%0], [%1], 16;" :: "r"(dst), "l"(src) : "memory");
}

static __device__ __forceinline__ void mbar_init(uint32_t a, uint32_t cnt) {
    asm volatile("mbarrier.init.shared.b64 [%0], %1;" :: "r"(a), "r"(cnt) : "memory");
}
static __device__ __forceinline__ void mbar_arrive(uint32_t a) {
    asm volatile("mbarrier.arrive.shared.b64 _, [%0];" :: "r"(a) : "memory");
}
static __device__ __forceinline__ void cp_arrive(uint32_t a) {
    // .noinc is load-bearing (plain form nets zero against the count)
    asm volatile("cp.async.mbarrier.arrive.noinc.shared.b64 [%0];" :: "r"(a) : "memory");
}
static __device__ __forceinline__ void mbar_wait(uint32_t a, uint32_t parity) {
    asm volatile(
        "{\n\t.reg .pred P;\n\t"
        "WL_%=:\n\t"
        "mbarrier.try_wait.parity.shared.b64 P, [%0], %1;\n\t"
        "@!P bra WL_%=;\n\t}"
        :: "r"(a), "r"(parity) : "memory");
}

static __device__ __forceinline__ void ldsm4(uint32_t* r, uint32_t addr) {
    asm volatile("ldmatrix.sync.aligned.m8n8.x4.shared.b16 {%0,%1,%2,%3}, [%4];"
                 : "=r"(r[0]), "=r"(r[1]), "=r"(r[2]), "=r"(r[3]) : "r"(addr));
}

static __device__ __forceinline__ void mma_f16(float* c, const uint32_t* a, const uint32_t* b) {
    asm volatile(
        "mma.sync.aligned.m16n8k16.row.col.f32.f16.f16.f32 "
        "{%0,%1,%2,%3}, {%4,%5,%6,%7}, {%8,%9}, {%0,%1,%2,%3};"
        : "+f"(c[0]), "+f"(c[1]), "+f"(c[2]), "+f"(c[3])
        : "r"(a[0]), "r"(a[1]), "r"(a[2]), "r"(a[3]), "r"(b[0]), "r"(b[1]));
}

static __device__ __forceinline__ float sigf(float x) { return 1.0f / (1.0f + __expf(-x)); }
static __device__ __forceinline__ float tanh_fast(float x) {
    return 2.0f / (1.0f + __expf(-2.0f * x)) - 1.0f;
}

// ---------------- merged pre-pass: all four tensors in ONE launch ----------------
__global__ void __launch_bounds__(256) preconv_all(const float4* __restrict__ s_h,
                                                   const float4* __restrict__ s_x,
                                                   const float4* __restrict__ s_wh,
                                                   const float4* __restrict__ s_wx) {
    const int T1 = NH / 8, T2 = T1 + NX / 8, T3 = T2 + NWH / 8, T4 = T3 + NWX / 8;
    int i = blockIdx.x * 256 + threadIdx.x;
    if (i >= T4) return;
    const float4* src;
    uint4* dst;
    int j = i;
    if (i < T1)      { src = s_h;  dst = (uint4*)g_h; }
    else if (i < T2) { src = s_x;  dst = (uint4*)g_x;  j = i - T1; }
    else if (i < T3) { src = s_wh; dst = (uint4*)g_wh; j = i - T2; }
    else             { src = s_wx; dst = (uint4*)g_wx; j = i - T3; }
    float4 a = src[2 * j], b = src[2 * j + 1];
    __half2 p0 = __floats2half2_rn(a.x, a.y);
    __half2 p1 = __floats2half2_rn(a.z, a.w);
    __half2 p2 = __floats2half2_rn(b.x, b.y);
    __half2 p3 = __floats2half2_rn(b.z, b.w);
    uint4 o;
    o.x = *reinterpret_cast<uint32_t*>(&p0);
    o.y = *reinterpret_cast<uint32_t*>(&p1);
    o.z = *reinterpret_cast<uint32_t*>(&p2);
    o.w = *reinterpret_cast<uint32_t*>(&p3);
    dst[j] = o;
}

// ---------------- chunk source resolution ----------------
static __device__ __forceinline__ void chunk_src(int chunk, const __half*& asrc,
                                                 const __half*& wk, int& ld,
                                                 int m_base) {
    if (chunk < 16) {                 // K in [0,1024): h_prev @ Wh^T
        asrc = g_h + (size_t)m_base * F_DIM + chunk * KC;
        wk   = g_wh + chunk * KC;
        ld   = F_DIM;
    } else {                          // K in [1024,1536): behavior @ Wx^T
        asrc = g_x + (size_t)m_base * B_DIM + (chunk - 16) * KC;
        wk   = g_wx + (chunk - 16) * KC;
        ld   = B_DIM;
    }
}

// A-half of a chunk load (8 cp16/thread at 128 threads)
static __device__ __forceinline__ void issue_A(int chunk, int slot, uint32_t sb, int tid,
                                               int m_base) {
    const __half *asrc, *wk; int ld;
    chunk_src(chunk, asrc, wk, ld, m_base);
    const uint32_t abase = sb + (uint32_t)slot * STAGE_BYTES;
#pragma unroll
    for (int i = 0; i < 8; ++i) {     // A: 128 rows x 128B, SW128 (1024 f4 units)
        int idx = tid + i * THREADS;
        int row = idx >> 3, u = idx & 7;
        cp16(abase + row * 128 + (uint32_t)((u ^ (row & 7)) << 4),
             asrc + (size_t)row * ld + u * 8);
    }
}

// B-half of a chunk load (8 cp16/thread)
static __device__ __forceinline__ void issue_B(int chunk, int slot, uint32_t sb, int tid,
                                               int m_base, int c_base) {
    const __half *asrc, *wk; int ld;
    chunk_src(chunk, asrc, wk, ld, m_base);
    const uint32_t bbase = sb + (uint32_t)slot * STAGE_BYTES + ABYTES;
#pragma unroll
    for (int i = 0; i < 8; ++i) {     // B: 128 rows x 128B, SW128
        int idx = tid + i * THREADS;
        int rr = idx >> 3, u = idx & 7;
        int g = rr >> 5, r = rr & 31;
        cp16(bbase + rr * 128 + (uint32_t)((u ^ (rr & 7)) << 4),
             wk + (size_t)(g * F_DIM + c_base + r) * ld + u * 8);
    }
}

__global__ void __launch_bounds__(THREADS, 2)
lstm_mma_kernel(float* __restrict__ out,
                const float* __restrict__ c_prev,
                const float* __restrict__ bias) {
    extern __shared__ char smem[];
    const uint32_t sb = smem_u32(smem);
    const int tid = threadIdx.x;
    const int lane = tid & 31;
    const int wid = tid >> 5;          // 4 warps
    const int warp_m = wid & 1;        // token half (64 rows)
    const int warp_n = wid >> 1;       // gemm-col half (64 cols = 2 gates)
    const int la = lane >> 2;          // 0..7
    const int lk = lane & 3;           // 0..3

    const int f_tile = blockIdx.x & 31;
    const int m_tile = blockIdx.x >> 5;
    const int m_base = m_tile * TILE_M;
    const int c_base = f_tile * TILE_F;

    // mbarriers: full[s] at SM_MBAR + 8s (count 128), empty[s] at +24+8s (count 4 warps)
    const uint32_t mb = sb + SM_MBAR;
    if (tid == 0) {
#pragma unroll
        for (int s = 0; s < 3; ++s) {
            mbar_init(mb + 8u * s, THREADS);
            mbar_init(mb + 24u + 8u * s, 4);
        }
    }
    float* bias_s = reinterpret_cast<float*>(smem + SM_BIAS);
    bias_s[tid] = bias[(tid >> 5) * F_DIM + c_base + (tid & 31)];
    __syncthreads();                   // mbarriers initialized

    // ---- per-lane ldmatrix address components ----
    const int q    = lane >> 3;        // quad / matrix index
    const int lrow = lane & 7;
    const uint32_t aStat = (uint32_t)(warp_m * 64 + (q & 1) * 8 + lrow) * 128u;
    const int kqA = q >> 1;
    const uint32_t bStat = (uint32_t)(warp_n * 64 + (q >> 1) * 8 + lrow) * 128u;
    const int kqB = q & 1;

    float acc[4][8][4];
#pragma unroll
    for (int mt = 0; mt < 4; ++mt)
#pragma unroll
        for (int nt = 0; nt < 8; ++nt)
#pragma unroll
            for (int j = 0; j < 4; ++j) acc[mt][nt][j] = 0.0f;

    // prologue: stages 0,1
    issue_A(0, 0, sb, tid, m_base); issue_B(0, 0, sb, tid, m_base, c_base);
    cp_arrive(mb + 0u);
    issue_A(1, 1, sb, tid, m_base); issue_B(1, 1, sb, tid, m_base, c_base);
    cp_arrive(mb + 8u);

    for (int blk = 0; blk < 8; ++blk) {
#pragma unroll
        for (int s = 0; s < 3; ++s) {
            const int ch = blk * 3 + s;
            const uint32_t pf = (uint32_t)(blk & 1);
            mbar_wait(mb + 8u * s, pf);          // chunk ch data ready

            const uint32_t abase = sb + (uint32_t)s * STAGE_BYTES;
            const uint32_t bbase = abase + ABYTES;
            const int c = ch + 2;                // chunk to prefetch
            const int cs = (s + 2) % 3;          // its stage
            const bool more = (c < NCHUNK);
            const uint32_t pe = (s == 0) ? (uint32_t)((blk - 1) & 1)
                                         : (uint32_t)(blk & 1);

#pragma unroll
            for (int ks = 0; ks < 4; ++ks) {     // 4 x K=16 per chunk
                const uint32_t uA = (uint32_t)(((2 * ks + kqA) ^ lrow) << 4);
                const uint32_t uB = (uint32_t)(((2 * ks + kqB) ^ lrow) << 4);

                uint32_t af[4][4];
                uint32_t bq[4][4];               // 4 x4-groups = 8 n-tiles
                ldsm4(af[0], abase + aStat + uA);
                ldsm4(bq[0], bbase + bStat + uB);
                ldsm4(af[1], abase + aStat + 2048u + uA);
                ldsm4(bq[1], bbase + bStat + 2048u + uB);
                ldsm4(af[2], abase + aStat + 4096u + uA);
                ldsm4(bq[2], bbase + bStat + 4096u + uB);
                ldsm4(af[3], abase + aStat + 6144u + uA);
                ldsm4(bq[3], bbase + bStat + 6144u + uB);

#pragma unroll
                for (int mt = 0; mt < 4; ++mt)
#pragma unroll
                    for (int nt = 0; nt < 8; ++nt)
                        mma_f16(acc[mt][nt], af[mt], &bq[nt >> 1][(nt & 1) * 2]);

                // spread next-chunk cp.async across the ks loop
                if (ks == 1 && more) {
                    if (c >= 3) mbar_wait(mb + 24u + 8u * cs, pe);  // stage free
                    issue_A(c, cs, sb, tid, m_base);
                }
                if (ks == 3 && more) {
                    issue_B(c, cs, sb, tid, m_base, c_base);
                    cp_arrive(mb + 8u * cs);
                }
            }

            if (lane == 0) mbar_arrive(mb + 24u + 8u * s);   // warp done with stage s
        }
    }

    __syncthreads();   // all warps done with stage buffers -> epilogue union

    // ---- epilogue: dump 4 gate tiles (128 x 32 each) to smem ----
    // gemm-col = warp_n*64 + nt*8 + 2lk(+1); gate = col>>5; f = col&31
    float* gsm = reinterpret_cast<float*>(smem);
#pragma unroll
    for (int mt = 0; mt < 4; ++mt) {
#pragma unroll
        for (int nt = 0; nt < 8; ++nt) {
            const int r0 = warp_m * 64 + mt * 16 + la;
            const int col0 = warp_n * 64 + nt * 8 + 2 * lk;
            const int gate = col0 >> 5;
            const int f0 = col0 & 31;
            const size_t o = ((size_t)(gate * 128 + r0)) * GSM_PITCH + f0;
            gsm[o]     = acc[mt][nt][0];
            gsm[o + 1] = acc[mt][nt][1];
            gsm[o + 8 * GSM_PITCH]     = acc[mt][nt][2];
            gsm[o + 8 * GSM_PITCH + 1] = acc[mt][nt][3];
        }
    }
    __syncthreads();

    // ---- gate math + coalesced global I/O ----
    const float* cpg = c_prev + (size_t)m_base * F_DIM + c_base;
    float* og = out + (size_t)m_base * F_DIM + c_base;
#pragma unroll
    for (int i = 0; i < (TILE_M * TILE_F) / THREADS; ++i) {
        const int idx = tid + i * THREADS;
        const int row = idx >> 5;
        const int f = idx & 31;
        const float cp = cpg[(size_t)row * F_DIM + f];
        const float xi = gsm[((size_t)(0 * 128 + row)) * GSM_PITCH + f] + bias_s[f];
        const float xf = gsm[((size_t)(1 * 128 + row)) * GSM_PITCH + f] + bias_s[32 + f];
        const float xg = gsm[((size_t)(2 * 128 + row)) * GSM_PITCH + f] + bias_s[64 + f];
        const float xo = gsm[((size_t)(3 * 128 + row)) * GSM_PITCH + f] + bias_s[96 + f];
        const float cv = sigf(xf) * cp + sigf(xi) * tanh_fast(xg);
        og[(size_t)row * F_DIM + f] = sigf(xo) * tanh_fast(cv);
    }
}

extern "C" void kernel_launch(void* const* d_in, const int* in_sizes, int n_in,
                              void* d_out, int out_size) {
    const float* behavior = (const float*)d_in[0];
    const float* h_prev   = (const float*)d_in[1];
    const float* c_prev   = (const float*)d_in[2];
    const float* Wh       = (const float*)d_in[3];
    const float* Wx       = (const float*)d_in[4];
    const float* bias     = (const float*)d_in[5];

    const int total8 = NH / 8 + NX / 8 + NWH / 8 + NWX / 8;
    preconv_all<<<(total8 + 255) / 256, 256>>>(
        (const float4*)h_prev, (const float4*)behavior,
        (const float4*)Wh, (const float4*)Wx);

    cudaFuncSetAttribute(lstm_mma_kernel,
                         cudaFuncAttributeMaxDynamicSharedMemorySize, SMEM_TOTAL);

    const int grid = (N_TOK / TILE_M) * (F_DIM / TILE_F);  // 128 * 32 = 4096
    lstm_mma_kernel<<<grid, THREADS, SMEM_TOTAL>>>((float*)d_out, c_prev, bias);
}

// round 15
// speedup vs baseline: 1.2412x; 1.2412x over previous
#include <cuda_runtime.h>
#include <cuda_fp16.h>
#include <cstdint>
#include <cstddef>

// Harness PTX target is base sm_103 — no tcgen05. Tensor path: mma.sync f16 m16n8k16
// (fallback HMMA, ~7.2 cyc/SMSP/inst -> ~341us busy floor). R13 structure (16 warps/SM,
// warp tile 64x32, 2 CTAs/SM, mbarrier pipeline) + hoisted address math + float2 epilogue.

// ---------------- problem constants ----------------
#define N_TOK   16384
#define F_DIM   1024
#define B_DIM   512
#define TILE_M  128
#define TILE_F  32
#define GCOLS   128          // 4 gates * TILE_F
#define KC      64           // K elements per chunk (128B fp16 rows)
#define NCHUNK  24           // 1536 / 64
#define THREADS 256
#define STAGES  3

// ---------------- smem layout ----------------
#define ABYTES      (TILE_M * KC * 2)          // 16384
#define BBYTES      (GCOLS * KC * 2)           // 16384
#define STAGE_BYTES (ABYTES + BBYTES)          // 32768
#define GSM_PITCH   36
#define GSM_BYTES   (4 * 128 * GSM_PITCH * 4)  // 73728 (epilogue, unions stages)
#define SM_BIAS     (STAGES * STAGE_BYTES)     // 98304
#define SM_MBAR     (SM_BIAS + 512)            // 6 mbarriers x 8B
#define SMEM_TOTAL  (SM_MBAR + 64)             // 98880  (x2 CTAs = 197760)

static_assert(GSM_BYTES <= STAGES * STAGE_BYTES, "epilogue union");
static_assert(2 * SMEM_TOTAL <= 227 * 1024, "2 CTAs/SM smem");

// ---------------- fp16 scratch ----------------
#define NH  (N_TOK * F_DIM)
#define NX  (N_TOK * B_DIM)
#define NWH (4 * F_DIM * F_DIM)
#define NWX (4 * F_DIM * B_DIM)
__device__ __half g_h [NH];
__device__ __half g_x [NX];
__device__ __half g_wh[NWH];
__device__ __half g_wx[NWX];

// ---------------- helpers ----------------
static __device__ __forceinline__ uint32_t smem_u32(const void* p) {
    uint32_t a;
    asm("{ .reg .u64 t; cvta.to.shared.u64 t, %1; cvt.u32.u64 %0, t; }" : "=r"(a) : "l"(p));
    return a;
}

static __device__ __forceinline__ void cp16(uint32_t dst, const void* src) {
    asm volatile("cp.async.cg.shared.global [%0], [%1], 16;" :: "r"(dst), "l"(src) : "memory");
}

static __device__ __forceinline__ void mbar_init(uint32_t a, uint32_t cnt) {
    asm volatile("mbarrier.init.shared.b64 [%0], %1;" :: "r"(a), "r"(cnt) : "memory");
}
static __device__ __forceinline__ void mbar_arrive(uint32_t a) {
    asm volatile("mbarrier.arrive.shared.b64 _, [%0];" :: "r"(a) : "memory");
}
static __device__ __forceinline__ void cp_arrive(uint32_t a) {
    // .noinc is load-bearing (plain form nets zero against the count)
    asm volatile("cp.async.mbarrier.arrive.noinc.shared.b64 [%0];" :: "r"(a) : "memory");
}
static __device__ __forceinline__ void mbar_wait(uint32_t a, uint32_t parity) {
    asm volatile(
        "{\n\t.reg .pred P;\n\t"
        "WL_%=:\n\t"
        "mbarrier.try_wait.parity.shared.b64 P, [%0], %1;\n\t"
        "@!P bra WL_%=;\n\t}"
        :: "r"(a), "r"(parity) : "memory");
}

static __device__ __forceinline__ void ldsm4(uint32_t* r, uint32_t addr) {
    asm volatile("ldmatrix.sync.aligned.m8n8.x4.shared.b16 {%0,%1,%2,%3}, [%4];"
                 : "=r"(r[0]), "=r"(r[1]), "=r"(r[2]), "=r"(r[3]) : "r"(addr));
}

static __device__ __forceinline__ void mma_f16(float* c, const uint32_t* a, const uint32_t* b) {
    asm volatile(
        "mma.sync.aligned.m16n8k16.row.col.f32.f16.f16.f32 "
        "{%0,%1,%2,%3}, {%4,%5,%6,%7}, {%8,%9}, {%0,%1,%2,%3};"
        : "+f"(c[0]), "+f"(c[1]), "+f"(c[2]), "+f"(c[3])
        : "r"(a[0]), "r"(a[1]), "r"(a[2]), "r"(a[3]), "r"(b[0]), "r"(b[1]));
}

static __device__ __forceinline__ float sigf(float x) { return 1.0f / (1.0f + __expf(-x)); }
static __device__ __forceinline__ float tanh_fast(float x) {
    return 2.0f / (1.0f + __expf(-2.0f * x)) - 1.0f;
}

// ---------------- merged pre-pass: all four tensors in ONE launch ----------------
__global__ void __launch_bounds__(256) preconv_all(const float4* __restrict__ s_h,
                                                   const float4* __restrict__ s_x,
                                                   const float4* __restrict__ s_wh,
                                                   const float4* __restrict__ s_wx) {
    const int T1 = NH / 8, T2 = T1 + NX / 8, T3 = T2 + NWH / 8, T4 = T3 + NWX / 8;
    int i = blockIdx.x * 256 + threadIdx.x;
    if (i >= T4) return;
    const float4* src;
    uint4* dst;
    int j = i;
    if (i < T1)      { src = s_h;  dst = (uint4*)g_h; }
    else if (i < T2) { src = s_x;  dst = (uint4*)g_x;  j = i - T1; }
    else if (i < T3) { src = s_wh; dst = (uint4*)g_wh; j = i - T2; }
    else             { src = s_wx; dst = (uint4*)g_wx; j = i - T3; }
    float4 a = src[2 * j], b = src[2 * j + 1];
    __half2 p0 = __floats2half2_rn(a.x, a.y);
    __half2 p1 = __floats2half2_rn(a.z, a.w);
    __half2 p2 = __floats2half2_rn(b.x, b.y);
    __half2 p3 = __floats2half2_rn(b.z, b.w);
    uint4 o;
    o.x = *reinterpret_cast<uint32_t*>(&p0);
    o.y = *reinterpret_cast<uint32_t*>(&p1);
    o.z = *reinterpret_cast<uint32_t*>(&p2);
    o.w = *reinterpret_cast<uint32_t*>(&p3);
    dst[j] = o;
}

// ---------------- chunk source resolution ----------------
static __device__ __forceinline__ void chunk_src(int chunk, const __half*& asrc,
                                                 const __half*& wk, int& ld,
                                                 int m_base) {
    if (chunk < 16) {                 // K in [0,1024): h_prev @ Wh^T
        asrc = g_h + (size_t)m_base * F_DIM + chunk * KC;
        wk   = g_wh + chunk * KC;
        ld   = F_DIM;
    } else {                          // K in [1024,1536): behavior @ Wx^T
        asrc = g_x + (size_t)m_base * B_DIM + (chunk - 16) * KC;
        wk   = g_wx + (chunk - 16) * KC;
        ld   = B_DIM;
    }
}

// A-half of a chunk load. dstA = per-thread stage-relative dst (hoisted swizzle).
// row r0 = tid>>3, 16B-unit u = tid&7, rows step by 32 -> dst step 4096, swz invariant.
static __device__ __forceinline__ void issue_A(int chunk, uint32_t dstA, int r0, int u8,
                                               int m_base) {
    const __half *asrc, *wk; int ld;
    chunk_src(chunk, asrc, wk, ld, m_base);
    const __half* s = asrc + (size_t)r0 * ld + u8;
#pragma unroll
    for (int i = 0; i < 4; ++i)
        cp16(dstA + (uint32_t)(i * 4096), s + (size_t)(i * 32) * ld);
}

// B-half: gate index == i, row-in-gate == r0 (exact for 256 threads).
static __device__ __forceinline__ void issue_B(int chunk, uint32_t dstB, int r0, int u8,
                                               int m_base, int c_base) {
    const __half *asrc, *wk; int ld;
    chunk_src(chunk, asrc, wk, ld, m_base);
    const __half* s = wk + (size_t)(c_base + r0) * ld + u8;
#pragma unroll
    for (int i = 0; i < 4; ++i)
        cp16(dstB + (uint32_t)(i * 4096), s + (size_t)(i * F_DIM) * ld);
}

__global__ void __launch_bounds__(THREADS, 2)
lstm_mma_kernel(float* __restrict__ out,
                const float* __restrict__ c_prev,
                const float* __restrict__ bias) {
    extern __shared__ char smem[];
    const uint32_t sb = smem_u32(smem);
    const int tid = threadIdx.x;
    const int lane = tid & 31;
    const int wid = tid >> 5;
    const int warp_m = wid & 1;        // token half (64 rows)
    const int warp_n = wid >> 1;       // gate (0..3), 32 gemm-cols each
    const int la = lane >> 2;          // 0..7
    const int lk = lane & 3;           // 0..3

    const int f_tile = blockIdx.x & 31;
    const int m_tile = blockIdx.x >> 5;
    const int m_base = m_tile * TILE_M;
    const int c_base = f_tile * TILE_F;

    // mbarriers: full[s] at SM_MBAR + 8s (count 256), empty[s] at +24+8s (count 8)
    const uint32_t mb = sb + SM_MBAR;
    if (tid == 0) {
#pragma unroll
        for (int s = 0; s < 3; ++s) {
            mbar_init(mb + 8u * s, 256);
            mbar_init(mb + 24u + 8u * s, 8);
        }
    }
    float* bias_s = reinterpret_cast<float*>(smem + SM_BIAS);
    if (tid < 128) bias_s[tid] = bias[(tid >> 5) * F_DIM + c_base + (tid & 31)];
    __syncthreads();                   // mbarriers initialized

    // ---- hoisted cp.async per-thread constants ----
    const int r0 = tid >> 3;           // 0..31
    const int u  = tid & 7;
    const int u8 = u * 8;
    const uint32_t swz = (uint32_t)((u ^ (r0 & 7)) << 4);
    const uint32_t dstA0 = sb + (uint32_t)r0 * 128 + swz;           // + slot*STAGE
    const uint32_t dstB0 = sb + ABYTES + (uint32_t)r0 * 128 + swz;  // rows step 32 = +4096

    // ---- hoisted ldmatrix per-lane constants ----
    const int q    = lane >> 3;
    const int lrow = lane & 7;
    const uint32_t aStat = (uint32_t)(warp_m * 64 + (q & 1) * 8 + lrow) * 128u;
    const uint32_t bStat = (uint32_t)(warp_n * 32 + (q >> 1) * 8 + lrow) * 128u;
    uint32_t uAk[4], uBk[4];           // loop-invariant swizzle terms
#pragma unroll
    for (int ks = 0; ks < 4; ++ks) {
        uAk[ks] = aStat + (uint32_t)(((2 * ks + (q >> 1)) ^ lrow) << 4);
        uBk[ks] = bStat + (uint32_t)(((2 * ks + (q & 1)) ^ lrow) << 4);
    }

    float acc[4][4][4];
#pragma unroll
    for (int mt = 0; mt < 4; ++mt)
#pragma unroll
        for (int nt = 0; nt < 4; ++nt)
#pragma unroll
            for (int j = 0; j < 4; ++j) acc[mt][nt][j] = 0.0f;

    // prologue: stages 0,1
    issue_A(0, dstA0, r0, u8, m_base); issue_B(0, dstB0, r0, u8, m_base, c_base);
    cp_arrive(mb + 0u);
    issue_A(1, dstA0 + STAGE_BYTES, r0, u8, m_base);
    issue_B(1, dstB0 + STAGE_BYTES, r0, u8, m_base, c_base);
    cp_arrive(mb + 8u);

    for (int blk = 0; blk < 8; ++blk) {
#pragma unroll
        for (int s = 0; s < 3; ++s) {
            const int ch = blk * 3 + s;
            const uint32_t pf = (uint32_t)(blk & 1);
            mbar_wait(mb + 8u * s, pf);          // chunk ch data ready

            const uint32_t abase = sb + (uint32_t)s * STAGE_BYTES;
            const uint32_t bbase = abase + ABYTES;
            const int c = ch + 2;                // chunk to prefetch
            const int cs = (s + 2) % 3;          // its stage
            const bool more = (c < NCHUNK);
            const uint32_t pe = (s == 0) ? (uint32_t)((blk - 1) & 1)
                                         : (uint32_t)(blk & 1);

#pragma unroll
            for (int ks = 0; ks < 4; ++ks) {     // 4 x K=16 per chunk
                uint32_t af[4][4];
                uint32_t bq[2][4];               // each x4 covers 2 n-tiles
                ldsm4(af[0], abase + uAk[ks]);
                ldsm4(bq[0], bbase + uBk[ks]);
                ldsm4(af[1], abase + uAk[ks] + 2048u);
                ldsm4(bq[1], bbase + uBk[ks] + 2048u);
                ldsm4(af[2], abase + uAk[ks] + 4096u);
                ldsm4(af[3], abase + uAk[ks] + 6144u);

#pragma unroll
                for (int mt = 0; mt < 4; ++mt)
#pragma unroll
                    for (int nt = 0; nt < 4; ++nt)
                        mma_f16(acc[mt][nt], af[mt], &bq[nt >> 1][(nt & 1) * 2]);

                // spread next-chunk cp.async across the ks loop
                if (ks == 1 && more) {
                    if (c >= 3) mbar_wait(mb + 24u + 8u * cs, pe);  // stage free
                    issue_A(c, dstA0 + (uint32_t)cs * STAGE_BYTES, r0, u8, m_base);
                }
                if (ks == 3 && more) {
                    issue_B(c, dstB0 + (uint32_t)cs * STAGE_BYTES, r0, u8, m_base, c_base);
                    cp_arrive(mb + 8u * cs);
                }
            }

            if (lane == 0) mbar_arrive(mb + 24u + 8u * s);   // warp done with stage s
        }
    }

    // ---- prefetch c_prev as float2 (latency hides under gsm writes) ----
    const float* cpg = c_prev + (size_t)m_base * F_DIM + c_base;
    float2 cpv[8];
#pragma unroll
    for (int j = 0; j < 8; ++j) {
        const int p = tid + j * THREADS;       // 2048 float2 slots
        const int row = p >> 4, f2 = p & 15;
        cpv[j] = *reinterpret_cast<const float2*>(cpg + (size_t)row * F_DIM + 2 * f2);
    }

    __syncthreads();   // all warps done with stage buffers -> epilogue union

    // ---- epilogue: dump 4 gate tiles (128 x 32 each) to smem, float2 stores ----
    float* gsm = reinterpret_cast<float*>(smem);
#pragma unroll
    for (int mt = 0; mt < 4; ++mt) {
#pragma unroll
        for (int nt = 0; nt < 4; ++nt) {
            const int rr = warp_m * 64 + mt * 16 + la;
            const int f0 = nt * 8 + 2 * lk;
            const size_t o = ((size_t)(warp_n * 128 + rr)) * GSM_PITCH + f0;
            *reinterpret_cast<float2*>(gsm + o) =
                make_float2(acc[mt][nt][0], acc[mt][nt][1]);
            *reinterpret_cast<float2*>(gsm + o + 8 * GSM_PITCH) =
                make_float2(acc[mt][nt][2], acc[mt][nt][3]);
        }
    }
    __syncthreads();

    // ---- gate math + coalesced global I/O, float2 throughout ----
    float* og = out + (size_t)m_base * F_DIM + c_base;
#pragma unroll
    for (int j = 0; j < 8; ++j) {
        const int p = tid + j * THREADS;
        const int row = p >> 4, f2 = p & 15;
        const int f = 2 * f2;
        const float2 xi = *reinterpret_cast<const float2*>(gsm + ((size_t)(0 * 128 + row)) * GSM_PITCH + f);
        const float2 xf = *reinterpret_cast<const float2*>(gsm + ((size_t)(1 * 128 + row)) * GSM_PITCH + f);
        const float2 xg = *reinterpret_cast<const float2*>(gsm + ((size_t)(2 * 128 + row)) * GSM_PITCH + f);
        const float2 xo = *reinterpret_cast<const float2*>(gsm + ((size_t)(3 * 128 + row)) * GSM_PITCH + f);
        const float2 bi = *reinterpret_cast<const float2*>(bias_s + f);
        const float2 bf = *reinterpret_cast<const float2*>(bias_s + 32 + f);
        const float2 bg = *reinterpret_cast<const float2*>(bias_s + 64 + f);
        const float2 bo = *reinterpret_cast<const float2*>(bias_s + 96 + f);
        float2 hv;
        {
            const float cv = sigf(xf.x + bf.x) * cpv[j].x + sigf(xi.x + bi.x) * tanh_fast(xg.x + bg.x);
            hv.x = sigf(xo.x + bo.x) * tanh_fast(cv);
        }
        {
            const float cv = sigf(xf.y + bf.y) * cpv[j].y + sigf(xi.y + bi.y) * tanh_fast(xg.y + bg.y);
            hv.y = sigf(xo.y + bo.y) * tanh_fast(cv);
        }
        *reinterpret_cast<float2*>(og + (size_t)row * F_DIM + f) = hv;
    }
}

extern "C" void kernel_launch(void* const* d_in, const int* in_sizes, int n_in,
                              void* d_out, int out_size) {
    const float* behavior = (const float*)d_in[0];
    const float* h_prev   = (const float*)d_in[1];
    const float* c_prev   = (const float*)d_in[2];
    const float* Wh       = (const float*)d_in[3];
    const float* Wx       = (const float*)d_in[4];
    const float* bias     = (const float*)d_in[5];

    const int total8 = NH / 8 + NX / 8 + NWH / 8 + NWX / 8;
    preconv_all<<<(total8 + 255) / 256, 256>>>(
        (const float4*)h_prev, (const float4*)behavior,
        (const float4*)Wh, (const float4*)Wx);

    cudaFuncSetAttribute(lstm_mma_kernel,
                         cudaFuncAttributeMaxDynamicSharedMemorySize, SMEM_TOTAL);

    const int grid = (N_TOK / TILE_M) * (F_DIM / TILE_F);  // 128 * 32 = 4096
    lstm_mma_kernel<<<grid, THREADS, SMEM_TOTAL>>>((float*)d_out, c_prev, bias);
}